// round 1
// baseline (speedup 1.0000x reference)
#include <cuda_runtime.h>

#define BB 16
#define LL 2048
#define DD 192
#define HH 4
#define KH 12
#define HK 48
#define LEPS 1e-3f
#define CR 16

// -------- scratch (no allocations allowed; __device__ globals) --------
__device__ float g_q[BB * HH * LL * KH];
__device__ float g_k[BB * HH * LL * KH];
__device__ float g_v[BB * HH * LL * KH];
__device__ float g_ctx[BB * HH * LL * KH];
__device__ float g_y1[BB * LL * DD];
__device__ float g_xn2[BB * LL * DD];
__device__ float g_hp[BB * LL * DD];

__device__ __forceinline__ float fast_ex2(float x) {
    float y; asm("ex2.approx.f32 %0, %1;" : "=f"(y) : "f"(x)); return y;
}

// ======================= K1: LN1 + QKV projection =======================
// grid = B*L blocks, 192 threads. Each block handles one token row.
__global__ void __launch_bounds__(DD) k_ln1_qkv(
    const float* __restrict__ x,
    const float* __restrict__ ln_g, const float* __restrict__ ln_b,
    const float* __restrict__ wq, const float* __restrict__ bq,
    const float* __restrict__ wk, const float* __restrict__ bk,
    const float* __restrict__ wv, const float* __restrict__ bv)
{
    __shared__ float xn[DD];
    __shared__ float red[8];
    const int row = blockIdx.x;
    const int tid = threadIdx.x;

    float xv = x[row * DD + tid];

    // mean
    float s = xv;
    #pragma unroll
    for (int o = 16; o > 0; o >>= 1) s += __shfl_xor_sync(0xffffffffu, s, o);
    if ((tid & 31) == 0) red[tid >> 5] = s;
    __syncthreads();
    float mean = (red[0] + red[1] + red[2] + red[3] + red[4] + red[5]) * (1.0f / DD);
    float d0 = xv - mean;
    __syncthreads();

    // variance
    float s2 = d0 * d0;
    #pragma unroll
    for (int o = 16; o > 0; o >>= 1) s2 += __shfl_xor_sync(0xffffffffu, s2, o);
    if ((tid & 31) == 0) red[tid >> 5] = s2;
    __syncthreads();
    float var = (red[0] + red[1] + red[2] + red[3] + red[4] + red[5]) * (1.0f / DD);
    float rstd = rsqrtf(var + LEPS);

    xn[tid] = d0 * rstd * ln_g[tid] + ln_b[tid];
    __syncthreads();

    if (tid < 3 * HK) {
        const int mat = tid / HK;      // 0=q, 1=k, 2=v
        const int j   = tid % HK;      // j = h*K + kk
        const float* w  = (mat == 0) ? wq : ((mat == 1) ? wk : wv);
        const float* bb = (mat == 0) ? bq : ((mat == 1) ? bk : bv);
        float acc = bb[j];
        #pragma unroll 8
        for (int d = 0; d < DD; d++) acc = fmaf(xn[d], w[d * HK + j], acc);
        float* dst = (mat == 0) ? g_q : ((mat == 1) ? g_k : g_v);
        const int bi = row / LL, l = row % LL;
        const int h = j / KH, kk = j % KH;
        dst[(((bi * HH + h) * LL) + l) * KH + kk] = acc;
    }
}

// ======================= K2: causal attention =======================
// One thread per query row; 128-query tiles; K/V streamed in 128-key smem
// tiles as float4. Scores are bounded (|s| ~ a few), so softmax without
// max-subtraction is exact in fp32.
__global__ void __launch_bounds__(128) k_attn()
{
    __shared__ float4 ks[128 * 3];
    __shared__ float4 vs[128 * 3];
    const int bh  = blockIdx.x;       // b*H + h
    const int qt  = blockIdx.y;       // query tile
    const int tid = threadIdx.x;
    const int l   = qt * 128 + tid;

    const float qsc = 0.41647020f;    // log2(e) / sqrt(12)
    float q[12];
    const float* qp = g_q + (bh * LL + l) * KH;
    #pragma unroll
    for (int i = 0; i < 12; i++) q[i] = qp[i] * qsc;

    float acc[12];
    #pragma unroll
    for (int i = 0; i < 12; i++) acc[i] = 0.f;
    float ssum = 0.f;

    for (int kt = 0; kt <= qt; kt++) {
        const float4* kp = (const float4*)(g_k + (bh * LL + kt * 128) * KH);
        const float4* vp = (const float4*)(g_v + (bh * LL + kt * 128) * KH);
        __syncthreads();              // previous tile fully consumed
        ks[tid * 3 + 0] = kp[tid * 3 + 0];
        ks[tid * 3 + 1] = kp[tid * 3 + 1];
        ks[tid * 3 + 2] = kp[tid * 3 + 2];
        vs[tid * 3 + 0] = vp[tid * 3 + 0];
        vs[tid * 3 + 1] = vp[tid * 3 + 1];
        vs[tid * 3 + 2] = vp[tid * 3 + 2];
        __syncthreads();

        const int mlim = (kt == qt) ? (tid + 1) : 128;
        #pragma unroll 2
        for (int m = 0; m < mlim; m++) {
            float4 ka = ks[m * 3 + 0], kb = ks[m * 3 + 1], kc = ks[m * 3 + 2];
            float s = q[0] * ka.x;
            s = fmaf(q[1], ka.y, s);  s = fmaf(q[2],  ka.z, s);  s = fmaf(q[3],  ka.w, s);
            s = fmaf(q[4], kb.x, s);  s = fmaf(q[5],  kb.y, s);  s = fmaf(q[6],  kb.z, s);
            s = fmaf(q[7], kb.w, s);  s = fmaf(q[8],  kc.x, s);  s = fmaf(q[9],  kc.y, s);
            s = fmaf(q[10], kc.z, s); s = fmaf(q[11], kc.w, s);
            float p = fast_ex2(s);
            ssum += p;
            float4 va = vs[m * 3 + 0], vb = vs[m * 3 + 1], vc = vs[m * 3 + 2];
            acc[0]  = fmaf(p, va.x, acc[0]);  acc[1]  = fmaf(p, va.y, acc[1]);
            acc[2]  = fmaf(p, va.z, acc[2]);  acc[3]  = fmaf(p, va.w, acc[3]);
            acc[4]  = fmaf(p, vb.x, acc[4]);  acc[5]  = fmaf(p, vb.y, acc[5]);
            acc[6]  = fmaf(p, vb.z, acc[6]);  acc[7]  = fmaf(p, vb.w, acc[7]);
            acc[8]  = fmaf(p, vc.x, acc[8]);  acc[9]  = fmaf(p, vc.y, acc[9]);
            acc[10] = fmaf(p, vc.z, acc[10]); acc[11] = fmaf(p, vc.w, acc[11]);
        }
    }
    const float inv = 1.0f / ssum;
    float* cp = g_ctx + (bh * LL + l) * KH;
    #pragma unroll
    for (int i = 0; i < 12; i++) cp[i] = acc[i] * inv;
}

// ======================= K3: out-proj + residual + LN2 =======================
__global__ void __launch_bounds__(DD) k_proj_ln2(
    const float* __restrict__ x,
    const float* __restrict__ wo, const float* __restrict__ bo,
    const float* __restrict__ g2, const float* __restrict__ b2)
{
    __shared__ float cs[HK];
    __shared__ float red[8];
    const int row = blockIdx.x;
    const int tid = threadIdx.x;
    const int bi = row / LL, l = row % LL;

    if (tid < HK) {
        const int h = tid / KH, kk = tid % KH;
        cs[tid] = g_ctx[((bi * HH + h) * LL + l) * KH + kk];
    }
    __syncthreads();

    float y = x[row * DD + tid] + bo[tid];
    #pragma unroll 8
    for (int j = 0; j < HK; j++) y = fmaf(cs[j], wo[j * DD + tid], y);
    g_y1[row * DD + tid] = y;

    // LN2
    float s = y;
    #pragma unroll
    for (int o = 16; o > 0; o >>= 1) s += __shfl_xor_sync(0xffffffffu, s, o);
    if ((tid & 31) == 0) red[tid >> 5] = s;
    __syncthreads();
    float mean = (red[0] + red[1] + red[2] + red[3] + red[4] + red[5]) * (1.0f / DD);
    float d0 = y - mean;
    __syncthreads();
    float s2 = d0 * d0;
    #pragma unroll
    for (int o = 16; o > 0; o >>= 1) s2 += __shfl_xor_sync(0xffffffffu, s2, o);
    if ((tid & 31) == 0) red[tid >> 5] = s2;
    __syncthreads();
    float var = (red[0] + red[1] + red[2] + red[3] + red[4] + red[5]) * (1.0f / DD);
    float rstd = rsqrtf(var + LEPS);

    g_xn2[row * DD + tid] = d0 * rstd * g2[tid] + b2[tid];
}

// ======================= K4: conv1 (3-tap, VALID) + bias + ReLU, padded =======================
// Output g_hp[b,l,:] = relu(conv) for l in [1, L-2], zero at l=0 and l=L-1.
__global__ void __launch_bounds__(DD) k_conv1(
    const float* __restrict__ w, const float* __restrict__ bias)
{
    __shared__ float ins[CR + 2][DD];
    const int b  = blockIdx.x;
    const int l0 = blockIdx.y * CR;
    const int tid = threadIdx.x;

    #pragma unroll
    for (int r = 0; r < CR + 2; r++) {
        const int li = l0 - 1 + r;
        ins[r][tid] = (li >= 0 && li < LL) ? g_xn2[(b * LL + li) * DD + tid] : 0.f;
    }
    __syncthreads();

    float acc[CR];
    #pragma unroll
    for (int r = 0; r < CR; r++) acc[r] = 0.f;

    for (int din = 0; din < DD; din++) {
        float xr[CR + 2];
        #pragma unroll
        for (int r = 0; r < CR + 2; r++) xr[r] = ins[r][din];
        #pragma unroll
        for (int t = 0; t < 3; t++) {
            const float wv = w[(t * DD + din) * DD + tid];
            #pragma unroll
            for (int r = 0; r < CR; r++) acc[r] = fmaf(xr[r + t], wv, acc[r]);
        }
    }

    const float bv = bias[tid];
    #pragma unroll
    for (int r = 0; r < CR; r++) {
        const int l = l0 + r;
        const float o = (l >= 1 && l < LL - 1) ? fmaxf(acc[r] + bv, 0.f) : 0.f;
        g_hp[(b * LL + l) * DD + tid] = o;
    }
}

// ======================= K5: conv2 + bias, padded, + residual =======================
__global__ void __launch_bounds__(DD) k_conv2(
    const float* __restrict__ w, const float* __restrict__ bias,
    float* __restrict__ out)
{
    __shared__ float ins[CR + 2][DD];
    const int b  = blockIdx.x;
    const int l0 = blockIdx.y * CR;
    const int tid = threadIdx.x;

    #pragma unroll
    for (int r = 0; r < CR + 2; r++) {
        const int li = l0 - 1 + r;
        ins[r][tid] = (li >= 0 && li < LL) ? g_hp[(b * LL + li) * DD + tid] : 0.f;
    }
    __syncthreads();

    float acc[CR];
    #pragma unroll
    for (int r = 0; r < CR; r++) acc[r] = 0.f;

    for (int din = 0; din < DD; din++) {
        float xr[CR + 2];
        #pragma unroll
        for (int r = 0; r < CR + 2; r++) xr[r] = ins[r][din];
        #pragma unroll
        for (int t = 0; t < 3; t++) {
            const float wv = w[(t * DD + din) * DD + tid];
            #pragma unroll
            for (int r = 0; r < CR; r++) acc[r] = fmaf(xr[r + t], wv, acc[r]);
        }
    }

    const float bv = bias[tid];
    #pragma unroll
    for (int r = 0; r < CR; r++) {
        const int l = l0 + r;
        const float base = g_y1[(b * LL + l) * DD + tid];
        out[(b * LL + l) * DD + tid] =
            (l >= 1 && l < LL - 1) ? (base + acc[r] + bv) : base;
    }
}

// ======================= launch =======================
extern "C" void kernel_launch(void* const* d_in, const int* in_sizes, int n_in,
                              void* d_out, int out_size)
{
    const float* x     = (const float*)d_in[0];
    const float* ln1_g = (const float*)d_in[1];
    const float* ln1_b = (const float*)d_in[2];
    const float* wq    = (const float*)d_in[3];
    const float* bq    = (const float*)d_in[4];
    const float* wk    = (const float*)d_in[5];
    const float* bk    = (const float*)d_in[6];
    const float* wv    = (const float*)d_in[7];
    const float* bv    = (const float*)d_in[8];
    const float* wo    = (const float*)d_in[9];
    const float* bo    = (const float*)d_in[10];
    const float* ln2_g = (const float*)d_in[11];
    const float* ln2_b = (const float*)d_in[12];
    const float* c1_w  = (const float*)d_in[13];
    const float* c1_b  = (const float*)d_in[14];
    const float* c2_w  = (const float*)d_in[15];
    const float* c2_b  = (const float*)d_in[16];
    float* out = (float*)d_out;

    k_ln1_qkv<<<BB * LL, DD>>>(x, ln1_g, ln1_b, wq, bq, wk, bk, wv, bv);
    dim3 ag(BB * HH, LL / 128);
    k_attn<<<ag, 128>>>();
    k_proj_ln2<<<BB * LL, DD>>>(x, wo, bo, ln2_g, ln2_b);
    dim3 cg(BB, LL / CR);
    k_conv1<<<cg, DD>>>(c1_w, c1_b);
    k_conv2<<<cg, DD>>>(c2_w, c2_b, out);
}

// round 2
// speedup vs baseline: 1.2439x; 1.2439x over previous
#include <cuda_runtime.h>

#define BB 16
#define LL 2048
#define DD 192
#define HH 4
#define KH 12
#define HK 48
#define LEPS 1e-3f
#define CR 16
#define RB 32

typedef unsigned long long u64;

// -------- scratch (no allocations allowed; __device__ globals) --------
__device__ float g_q[BB * HH * LL * KH];
__device__ float g_k[BB * HH * LL * KH];
__device__ float g_v[BB * HH * LL * KH];
__device__ float g_ctx[BB * HH * LL * KH];
__device__ float g_y1[BB * LL * DD];
__device__ float g_xn2[BB * LL * DD];
__device__ float g_hp[BB * LL * DD];

// -------- packed fp32x2 helpers (Blackwell FFMA2 path) --------
__device__ __forceinline__ u64 ffma2(u64 a, u64 b, u64 c) {
    u64 d; asm("fma.rn.f32x2 %0, %1, %2, %3;" : "=l"(d) : "l"(a), "l"(b), "l"(c));
    return d;
}
__device__ __forceinline__ u64 fmul2(u64 a, u64 b) {
    u64 d; asm("mul.rn.f32x2 %0, %1, %2;" : "=l"(d) : "l"(a), "l"(b));
    return d;
}
__device__ __forceinline__ u64 pack2(float lo, float hi) {
    u64 r; asm("mov.b64 %0, {%1, %2};" : "=l"(r) : "f"(lo), "f"(hi));
    return r;
}
__device__ __forceinline__ float2 unpack2(u64 v) {
    float2 f; asm("mov.b64 {%0, %1}, %2;" : "=f"(f.x), "=f"(f.y) : "l"(v));
    return f;
}
__device__ __forceinline__ float fast_ex2(float x) {
    float y; asm("ex2.approx.f32 %0, %1;" : "=f"(y) : "f"(x)); return y;
}

// ======================= K1: LN1 + QKV projection =======================
// 32 rows per block, 288 threads. x stored TRANSPOSED in smem so row-pairs
// are aligned LDS.64 operands for FFMA2. GEMM: thread = (j of 144, rowgroup
// of 2), 16 rows (8 row-pairs) each.
__global__ void __launch_bounds__(288) k_ln1_qkv(
    const float* __restrict__ x,
    const float* __restrict__ ln_g, const float* __restrict__ ln_b,
    const float* __restrict__ wq, const float* __restrict__ bq,
    const float* __restrict__ wk, const float* __restrict__ bk,
    const float* __restrict__ wv, const float* __restrict__ bv)
{
    __shared__ float xsT[DD][RB + 2];      // stride 34 floats: 8B-aligned rows
    __shared__ float mean_s[RB], rstd_s[RB];
    const int row0 = blockIdx.x * RB;
    const int tid  = threadIdx.x;

    // load transposed (coalesced LDG, ~2-way smem store conflicts: fine)
    for (int idx = tid; idx < RB * DD; idx += 288) {
        const int r = idx / DD, c = idx - r * DD;
        xsT[c][r] = x[(row0 + r) * DD + c];
    }
    __syncthreads();

    // per-row mean/var: thread t handles row t (conflict-free LDS across lanes)
    if (tid < RB) {
        float s = 0.f, s2 = 0.f;
        #pragma unroll 8
        for (int c = 0; c < DD; c++) {
            const float v = xsT[c][tid];
            s += v; s2 = fmaf(v, v, s2);
        }
        const float m = s * (1.0f / DD);
        const float var = s2 * (1.0f / DD) - m * m;
        mean_s[tid] = m;
        rstd_s[tid] = rsqrtf(var + LEPS);
    }
    __syncthreads();

    // normalize in place
    for (int idx = tid; idx < RB * DD; idx += 288) {
        const int r = idx & (RB - 1), c = idx >> 5;
        xsT[c][r] = (xsT[c][r] - mean_s[r]) * rstd_s[r] * ln_g[c] + ln_b[c];
    }
    __syncthreads();

    // GEMM: 144 output columns (q|k|v x 48) x 2 row-groups
    const int jj = tid % 144;
    const int rg = tid / 144;              // 0 or 1
    const int m  = jj / HK;
    const int j  = jj - m * HK;
    const float* w  = (m == 0) ? wq : (m == 1) ? wk : wv;
    const float* bb = (m == 0) ? bq : (m == 1) ? bk : bv;
    const float bias = bb[j];
    const int rbase = rg * 16;

    u64 acc[8];
    const u64 binit = pack2(bias, bias);
    #pragma unroll
    for (int p = 0; p < 8; p++) acc[p] = binit;

    #pragma unroll 4
    for (int d = 0; d < DD; d++) {
        const float wv_ = w[d * HK + j];
        const u64 w2 = pack2(wv_, wv_);
        const u64* xp = (const u64*)&xsT[d][rbase];
        #pragma unroll
        for (int p = 0; p < 8; p++) acc[p] = ffma2(xp[p], w2, acc[p]);
    }

    float* dst = (m == 0) ? g_q : (m == 1) ? g_k : g_v;
    const int bi = row0 / LL;
    const int l0 = row0 - bi * LL;
    const int h = j / KH, kk = j - h * KH;
    float* o = dst + (((bi * HH + h) * LL) + l0 + rbase) * KH + kk;
    #pragma unroll
    for (int p = 0; p < 8; p++) {
        const float2 f = unpack2(acc[p]);
        o[(2 * p) * KH]     = f.x;
        o[(2 * p + 1) * KH] = f.y;
    }
}

// ======================= K2: causal attention (FFMA2) =======================
// One thread per query row; 128-key smem tiles. K/V rows = 12 contiguous
// floats -> aligned LDS.64 pairs. Scores bounded -> no max-subtraction.
__global__ void __launch_bounds__(128) k_attn()
{
    __shared__ float ks[128 * 12];
    __shared__ float vs[128 * 12];
    const int bh  = blockIdx.x;
    const int qt  = blockIdx.y;
    const int tid = threadIdx.x;
    const int l   = qt * 128 + tid;

    const float qsc = 0.41647020f;    // log2(e) / sqrt(12)
    const u64 qsc2 = pack2(qsc, qsc);
    u64 q2[6];
    {
        const u64* qp = (const u64*)(g_q + (bh * LL + l) * KH);
        #pragma unroll
        for (int i = 0; i < 6; i++) q2[i] = fmul2(qp[i], qsc2);
    }

    u64 acc[6];
    #pragma unroll
    for (int i = 0; i < 6; i++) acc[i] = 0ull;
    float ssum = 0.f;

    for (int kt = 0; kt <= qt; kt++) {
        const float4* kp4 = (const float4*)(g_k + (bh * LL + kt * 128) * KH);
        const float4* vp4 = (const float4*)(g_v + (bh * LL + kt * 128) * KH);
        __syncthreads();
        ((float4*)ks)[tid * 3 + 0] = kp4[tid * 3 + 0];
        ((float4*)ks)[tid * 3 + 1] = kp4[tid * 3 + 1];
        ((float4*)ks)[tid * 3 + 2] = kp4[tid * 3 + 2];
        ((float4*)vs)[tid * 3 + 0] = vp4[tid * 3 + 0];
        ((float4*)vs)[tid * 3 + 1] = vp4[tid * 3 + 1];
        ((float4*)vs)[tid * 3 + 2] = vp4[tid * 3 + 2];
        __syncthreads();

        const int mlim = (kt == qt) ? (tid + 1) : 128;
        for (int m = 0; m < mlim; m++) {
            const u64* kp = (const u64*)(ks + m * 12);
            const u64* vp = (const u64*)(vs + m * 12);
            u64 s2 = ffma2(q2[0], kp[0], 0ull);
            s2 = ffma2(q2[1], kp[1], s2);
            s2 = ffma2(q2[2], kp[2], s2);
            s2 = ffma2(q2[3], kp[3], s2);
            s2 = ffma2(q2[4], kp[4], s2);
            s2 = ffma2(q2[5], kp[5], s2);
            const float2 sf = unpack2(s2);
            const float p = fast_ex2(sf.x + sf.y);
            ssum += p;
            const u64 p2 = pack2(p, p);
            acc[0] = ffma2(p2, vp[0], acc[0]);
            acc[1] = ffma2(p2, vp[1], acc[1]);
            acc[2] = ffma2(p2, vp[2], acc[2]);
            acc[3] = ffma2(p2, vp[3], acc[3]);
            acc[4] = ffma2(p2, vp[4], acc[4]);
            acc[5] = ffma2(p2, vp[5], acc[5]);
        }
    }
    const float inv = 1.0f / ssum;
    const u64 inv2 = pack2(inv, inv);
    u64* cp = (u64*)(g_ctx + (bh * LL + l) * KH);
    #pragma unroll
    for (int i = 0; i < 6; i++) cp[i] = fmul2(acc[i], inv2);
}

// ======================= K3: out-proj + residual + LN2 =======================
__global__ void __launch_bounds__(DD) k_proj_ln2(
    const float* __restrict__ x,
    const float* __restrict__ wo, const float* __restrict__ bo,
    const float* __restrict__ g2, const float* __restrict__ b2)
{
    __shared__ float cs[HK];
    __shared__ float red[8];
    const int row = blockIdx.x;
    const int tid = threadIdx.x;
    const int bi = row / LL, l = row % LL;

    if (tid < HK) {
        const int h = tid / KH, kk = tid % KH;
        cs[tid] = g_ctx[((bi * HH + h) * LL + l) * KH + kk];
    }
    __syncthreads();

    float y = x[row * DD + tid] + bo[tid];
    #pragma unroll 8
    for (int j = 0; j < HK; j++) y = fmaf(cs[j], wo[j * DD + tid], y);
    g_y1[row * DD + tid] = y;

    float s = y;
    #pragma unroll
    for (int o = 16; o > 0; o >>= 1) s += __shfl_xor_sync(0xffffffffu, s, o);
    if ((tid & 31) == 0) red[tid >> 5] = s;
    __syncthreads();
    const float mean = (red[0] + red[1] + red[2] + red[3] + red[4] + red[5]) * (1.0f / DD);
    const float d0 = y - mean;
    __syncthreads();
    float s2 = d0 * d0;
    #pragma unroll
    for (int o = 16; o > 0; o >>= 1) s2 += __shfl_xor_sync(0xffffffffu, s2, o);
    if ((tid & 31) == 0) red[tid >> 5] = s2;
    __syncthreads();
    const float var = (red[0] + red[1] + red[2] + red[3] + red[4] + red[5]) * (1.0f / DD);
    const float rstd = rsqrtf(var + LEPS);

    g_xn2[row * DD + tid] = d0 * rstd * g2[tid] + b2[tid];
}

// ======================= K4: conv1 + bias + ReLU (FFMA2, dout-pairs) =======================
__global__ void __launch_bounds__(192) k_conv1(
    const float* __restrict__ w, const float* __restrict__ bias)
{
    __shared__ float ins[CR + 2][DD];
    const int b   = blockIdx.x;
    const int l0  = blockIdx.y * CR;
    const int tid = threadIdx.x;

    #pragma unroll
    for (int r = 0; r < CR + 2; r++) {
        const int li = l0 - 1 + r;
        ins[r][tid] = (li >= 0 && li < LL) ? g_xn2[(b * LL + li) * DD + tid] : 0.f;
    }
    __syncthreads();

    const int dp = tid % 96;           // dout pair
    const int rg = tid / 96;           // row group 0/1 (whole warps)
    const int d0 = dp * 2;
    const int rb = rg * 8;

    u64 acc[8];
    #pragma unroll
    for (int r = 0; r < 8; r++) acc[r] = 0ull;

    for (int din = 0; din < DD; din++) {
        u64 xb[10];
        #pragma unroll
        for (int i = 0; i < 10; i++) {
            const float xv_ = ins[rb + i][din];     // warp-uniform: broadcast
            xb[i] = pack2(xv_, xv_);
        }
        #pragma unroll
        for (int t = 0; t < 3; t++) {
            const u64 w2 = *(const u64*)(w + (t * DD + din) * DD + d0);  // LDG.64
            #pragma unroll
            for (int r = 0; r < 8; r++) acc[r] = ffma2(xb[r + t], w2, acc[r]);
        }
    }

    const float2 bv2 = *(const float2*)&bias[d0];
    #pragma unroll
    for (int r = 0; r < 8; r++) {
        const int l = l0 + rb + r;
        const float2 a = unpack2(acc[r]);
        const bool in = (l >= 1 && l < LL - 1);
        float2 o;
        o.x = in ? fmaxf(a.x + bv2.x, 0.f) : 0.f;
        o.y = in ? fmaxf(a.y + bv2.y, 0.f) : 0.f;
        *(float2*)&g_hp[(b * LL + l) * DD + d0] = o;
    }
}

// ======================= K5: conv2 + bias + residual (FFMA2) =======================
__global__ void __launch_bounds__(192) k_conv2(
    const float* __restrict__ w, const float* __restrict__ bias,
    float* __restrict__ out)
{
    __shared__ float ins[CR + 2][DD];
    const int b   = blockIdx.x;
    const int l0  = blockIdx.y * CR;
    const int tid = threadIdx.x;

    #pragma unroll
    for (int r = 0; r < CR + 2; r++) {
        const int li = l0 - 1 + r;
        ins[r][tid] = (li >= 0 && li < LL) ? g_hp[(b * LL + li) * DD + tid] : 0.f;
    }
    __syncthreads();

    const int dp = tid % 96;
    const int rg = tid / 96;
    const int d0 = dp * 2;
    const int rb = rg * 8;

    u64 acc[8];
    #pragma unroll
    for (int r = 0; r < 8; r++) acc[r] = 0ull;

    for (int din = 0; din < DD; din++) {
        u64 xb[10];
        #pragma unroll
        for (int i = 0; i < 10; i++) {
            const float xv_ = ins[rb + i][din];
            xb[i] = pack2(xv_, xv_);
        }
        #pragma unroll
        for (int t = 0; t < 3; t++) {
            const u64 w2 = *(const u64*)(w + (t * DD + din) * DD + d0);
            #pragma unroll
            for (int r = 0; r < 8; r++) acc[r] = ffma2(xb[r + t], w2, acc[r]);
        }
    }

    const float2 bv2 = *(const float2*)&bias[d0];
    #pragma unroll
    for (int r = 0; r < 8; r++) {
        const int l = l0 + rb + r;
        const float2 a = unpack2(acc[r]);
        const float2 base = *(const float2*)&g_y1[(b * LL + l) * DD + d0];
        const bool in = (l >= 1 && l < LL - 1);
        float2 o;
        o.x = in ? (base.x + a.x + bv2.x) : base.x;
        o.y = in ? (base.y + a.y + bv2.y) : base.y;
        *(float2*)&out[(b * LL + l) * DD + d0] = o;
    }
}

// ======================= launch =======================
extern "C" void kernel_launch(void* const* d_in, const int* in_sizes, int n_in,
                              void* d_out, int out_size)
{
    const float* x     = (const float*)d_in[0];
    const float* ln1_g = (const float*)d_in[1];
    const float* ln1_b = (const float*)d_in[2];
    const float* wq    = (const float*)d_in[3];
    const float* bq    = (const float*)d_in[4];
    const float* wk    = (const float*)d_in[5];
    const float* bk    = (const float*)d_in[6];
    const float* wv    = (const float*)d_in[7];
    const float* bv    = (const float*)d_in[8];
    const float* wo    = (const float*)d_in[9];
    const float* bo    = (const float*)d_in[10];
    const float* ln2_g = (const float*)d_in[11];
    const float* ln2_b = (const float*)d_in[12];
    const float* c1_w  = (const float*)d_in[13];
    const float* c1_b  = (const float*)d_in[14];
    const float* c2_w  = (const float*)d_in[15];
    const float* c2_b  = (const float*)d_in[16];
    float* out = (float*)d_out;

    k_ln1_qkv<<<BB * LL / RB, 288>>>(x, ln1_g, ln1_b, wq, bq, wk, bk, wv, bv);
    dim3 ag(BB * HH, LL / 128);
    k_attn<<<ag, 128>>>();
    k_proj_ln2<<<BB * LL, DD>>>(x, wo, bo, ln2_g, ln2_b);
    dim3 cg(BB, LL / CR);
    k_conv1<<<cg, 192>>>(c1_w, c1_b);
    k_conv2<<<cg, 192>>>(c2_w, c2_b, out);
}